// round 10
// baseline (speedup 1.0000x reference)
#include <cuda_runtime.h>
#include <cuda_bf16.h>
#include <cstdint>

#define N_NODES 50000
#define FEAT 128
#define NRELS 4
#define EMAXCAP 262144

// Scratch (static __device__ — no allocation allowed)
__device__ int g_deg[NRELS][N_NODES];          // per-relation in-degree
__device__ int g_off[NRELS][N_NODES];          // CSR exclusive offsets
__device__ int g_cur[NRELS][N_NODES];          // fill cursors (copy of off)
__device__ int g_esrc[NRELS][EMAXCAP];         // CSR edge source ids
__device__ unsigned short g_Wb[NRELS * FEAT * FEAT];   // composed W^T [r][n][k], bf16 big
__device__ unsigned short g_Ws[NRELS * FEAT * FEAT];   // composed W^T [r][n][k], bf16 small

// ---------------------------------------------------------------------------
// helpers
// ---------------------------------------------------------------------------
__device__ __forceinline__ uint32_t smem_u32(const void* p) {
    uint32_t a;
    asm("{ .reg .u64 t; cvta.to.shared.u64 t, %1; cvt.u32.u64 %0, t; }" : "=r"(a) : "l"(p));
    return a;
}
__device__ __forceinline__ unsigned short f2bf(float x) {
    return __bfloat16_as_ushort(__float2bfloat16_rn(x));
}
__device__ __forceinline__ float bf2f(unsigned short u) {
    return __uint_as_float(((uint32_t)u) << 16);
}
__device__ __forceinline__ void ldsm4(uint32_t* r, uint32_t addr) {
    asm volatile("ldmatrix.sync.aligned.m8n8.x4.shared.b16 {%0,%1,%2,%3}, [%4];"
                 : "=r"(r[0]), "=r"(r[1]), "=r"(r[2]), "=r"(r[3]) : "r"(addr));
}
__device__ __forceinline__ void mma_bf16(float* d, const uint32_t* a, uint32_t b0, uint32_t b1) {
    asm volatile(
        "mma.sync.aligned.m16n8k16.row.col.f32.bf16.bf16.f32 "
        "{%0,%1,%2,%3}, {%4,%5,%6,%7}, {%8,%9}, {%0,%1,%2,%3};"
        : "+f"(d[0]), "+f"(d[1]), "+f"(d[2]), "+f"(d[3])
        : "r"(a[0]), "r"(a[1]), "r"(a[2]), "r"(a[3]), "r"(b0), "r"(b1));
}
__device__ __forceinline__ void cp_async16(uint32_t smem_dst, const void* gsrc) {
    asm volatile("cp.async.cg.shared.global [%0], [%1], 16;"
                 :: "r"(smem_dst), "l"(gsrc) : "memory");
}
#define SWZ(off) ((off) ^ (((off) >> 3) & 0x70))

// ---------------------------------------------------------------------------
// W precompute: W^T[r][n][k] composed from bases, split to bf16 big + small
// ---------------------------------------------------------------------------
__global__ void compute_w_kernel(const float* __restrict__ weight,
                                 const float* __restrict__ w_comp) {
    int idx = blockIdx.x * blockDim.x + threadIdx.x;   // 4 * 16384, idx = r*16384 + n*128 + k
    int r = idx >> 14;
    int k = idx & 127;
    int n = (idx >> 7) & 127;
    float w = w_comp[r * 2 + 0] * weight[k * 128 + n]
            + w_comp[r * 2 + 1] * weight[16384 + k * 128 + n];
    unsigned short big = f2bf(w);
    g_Wb[idx] = big;
    g_Ws[idx] = f2bf(w - bf2f(big));
}

// ---------------------------------------------------------------------------
// CSR build: count -> scan -> fill
// ---------------------------------------------------------------------------
__global__ void count_kernel(const int* __restrict__ d0, const int* __restrict__ d1,
                             const int* __restrict__ d2, const int* __restrict__ d3,
                             int E0, int E1, int E2, int E3) {
    int rel = blockIdx.y;
    int e = blockIdx.x * 256 + threadIdx.x;
    const int* dp = (rel == 0) ? d0 : (rel == 1) ? d1 : (rel == 2) ? d2 : d3;
    int E = (rel == 0) ? E0 : (rel == 1) ? E1 : (rel == 2) ? E2 : E3;
    if (e < E) {
        int d = __ldg(dp + e);
        if (d >= 0 && d < N_NODES) atomicAdd(&g_deg[rel][d], 1);
    }
}

__global__ void __launch_bounds__(1024)
scan_kernel() {
    int rel = blockIdx.x;
    __shared__ int sums[1024];
    int tid = threadIdx.x;
    const int CH = 49;                       // 49*1024 = 50176 >= 50000
    int bs = tid * CH;
    int s = 0;
    for (int i = 0; i < CH; i++) {
        int idx = bs + i;
        if (idx < N_NODES) s += g_deg[rel][idx];
    }
    sums[tid] = s;
    __syncthreads();
    for (int d = 1; d < 1024; d <<= 1) {     // Hillis-Steele inclusive scan
        int v = (tid >= d) ? sums[tid - d] : 0;
        __syncthreads();
        sums[tid] += v;
        __syncthreads();
    }
    int run = (tid == 0) ? 0 : sums[tid - 1];
    for (int i = 0; i < CH; i++) {
        int idx = bs + i;
        if (idx < N_NODES) {
            g_off[rel][idx] = run;
            g_cur[rel][idx] = run;
            run += g_deg[rel][idx];
        }
    }
}

__global__ void fill_kernel(const int* __restrict__ s0, const int* __restrict__ d0,
                            const int* __restrict__ s1, const int* __restrict__ d1,
                            const int* __restrict__ s2, const int* __restrict__ d2,
                            const int* __restrict__ s3, const int* __restrict__ d3,
                            int E0, int E1, int E2, int E3) {
    int rel = blockIdx.y;
    int e = blockIdx.x * 256 + threadIdx.x;
    const int* sp = (rel == 0) ? s0 : (rel == 1) ? s1 : (rel == 2) ? s2 : s3;
    const int* dp = (rel == 0) ? d0 : (rel == 1) ? d1 : (rel == 2) ? d2 : d3;
    int E = (rel == 0) ? E0 : (rel == 1) ? E1 : (rel == 2) ? E2 : E3;
    if (e < E) {
        int d = __ldg(dp + e);
        if (d >= 0 && d < N_NODES) {
            int slot = atomicAdd(&g_cur[rel][d], 1);
            if (slot >= 0 && slot < EMAXCAP) g_esrc[rel][slot] = __ldg(sp + e);
        }
    }
}

// ---------------------------------------------------------------------------
// Fused aggregate + bf16 mma.sync GEMM (big/small compensation, 3 products).
// CTA tile M=64 x N=128, 4 chunks (2 rels x 2 kchunks of 64). A is built
// in-SMEM directly from CSR edge gathers (no g_A intermediate): warp per dst
// row, MLP-4 edge batches, fp32 register sum -> bf16 split -> STS.
// smem/chunk = A 2x8KB + B 2x16KB = 48KB -> occ 2. B staged via cp.async,
// issued before aggregation so it overlaps the gather latency.
// 8 warps as 2(M) x 4(N); warp tile 32x32.
// ---------------------------------------------------------------------------
#define SM_AB 0
#define SM_AS 8192
#define SM_BB 16384
#define SM_BS 32768
#define SMEM_BYTES 49152

__global__ void __launch_bounds__(256, 2)
gemm_kernel(const float* __restrict__ x0, const float* __restrict__ x1,
            const float* __restrict__ bias, float* __restrict__ out) {
    extern __shared__ char smem_raw[];
    const uint32_t base = smem_u32(smem_raw);

    const int t = blockIdx.y;
    const int row0 = blockIdx.x * 64;
    const int tid = threadIdx.x;
    const int lane = tid & 31;
    const int warp = tid >> 5;
    const int m0 = (warp & 1) * 32;      // warp row offset in 64-row tile
    const int n0 = (warp >> 1) * 32;     // warp col offset in 128-col tile

    float acc[2][4][4];
    #pragma unroll
    for (int mf = 0; mf < 2; mf++)
        #pragma unroll
        for (int nf = 0; nf < 4; nf++)
            #pragma unroll
            for (int i = 0; i < 4; i++) acc[mf][nf][i] = 0.f;

    // ldmatrix lane addressing (8x8 tile rows), hoisted
    const int lrow = (lane & 7) + 8 * ((lane >> 3) & 1);
    const int lkb  = (lane >> 4) * 8;

    #pragma unroll 1
    for (int c = 0; c < 4; c++) {
        const int rel = t + (c >> 1) * 2;
        const int kc = c & 1;
        const float* x = (rel < 2) ? x0 : x1;
        const unsigned short* WBb = g_Wb + rel * FEAT * FEAT;
        const unsigned short* WSb = g_Ws + rel * FEAT * FEAT;
        const int kbase = kc * 64;

        if (c) __syncthreads();          // previous compute done before restage

        // ---- B chunk via cp.async first (overlaps edge gathers below) ----
        #pragma unroll
        for (int j = 0; j < 4; j++) {
            int i = tid + j * 256;            // 1024 groups of 8 bf16
            int n = i >> 3;                   // 0..127
            int kq = i & 7;
            uint32_t sw = SWZ((uint32_t)(n * 128 + kq * 16));
            cp_async16(base + SM_BB + sw, WBb + n * FEAT + kbase + kq * 8);
            cp_async16(base + SM_BS + sw, WSb + n * FEAT + kbase + kq * 8);
        }
        asm volatile("cp.async.commit_group;" ::: "memory");

        // ---- aggregate A chunk from CSR: warp per row, 8 rows/warp ----
        #pragma unroll 1
        for (int rr = 0; rr < 8; rr++) {
            int r = warp * 8 + rr;
            int g = row0 + r;
            float2 a2 = make_float2(0.f, 0.f);
            if (g < N_NODES) {
                int eb = __ldg(&g_off[rel][g]);
                int dg = __ldg(&g_deg[rel][g]);
                const int* ep = &g_esrc[rel][eb];
                for (int e = 0; e < dg; e += 4) {
                    int m = dg - e; if (m > 4) m = 4;
                    int srcs[4]; float2 v[4];
                    #pragma unroll
                    for (int q = 0; q < 4; q++)
                        if (q < m) srcs[q] = __ldg(ep + e + q);
                    #pragma unroll
                    for (int q = 0; q < 4; q++)
                        if (q < m) v[q] = __ldg(reinterpret_cast<const float2*>(
                                x + (size_t)srcs[q] * FEAT + kbase) + lane);
                    #pragma unroll
                    for (int q = 0; q < 4; q++)
                        if (q < m) { a2.x += v[q].x; a2.y += v[q].y; }
                }
            }
            unsigned short b0 = f2bf(a2.x), b1 = f2bf(a2.y);
            unsigned short s0 = f2bf(a2.x - bf2f(b0)), s1 = f2bf(a2.y - bf2f(b1));
            uint32_t Bp = ((uint32_t)b1 << 16) | b0;
            uint32_t Sp = ((uint32_t)s1 << 16) | s0;
            uint32_t sw = SWZ((uint32_t)(r * 128 + lane * 4));
            asm volatile("st.shared.b32 [%0], %1;" :: "r"(base + SM_AB + sw), "r"(Bp) : "memory");
            asm volatile("st.shared.b32 [%0], %1;" :: "r"(base + SM_AS + sw), "r"(Sp) : "memory");
        }
        asm volatile("cp.async.wait_group 0;" ::: "memory");
        __syncthreads();

        // ---- compute: 4 k16 steps ----
        #pragma unroll
        for (int ks = 0; ks < 4; ks++) {
            const int kk0 = ks * 16;

            uint32_t aB[2][4], aS[2][4];
            #pragma unroll
            for (int mf = 0; mf < 2; mf++) {
                uint32_t sw = SWZ((uint32_t)((m0 + mf * 16 + lrow) * 128 + (kk0 + lkb) * 2));
                ldsm4(aB[mf], base + SM_AB + sw);
                ldsm4(aS[mf], base + SM_AS + sw);
            }
            uint32_t bB[2][4], bS[2][4];
            #pragma unroll
            for (int ng = 0; ng < 2; ng++) {
                uint32_t sw = SWZ((uint32_t)((n0 + ng * 16 + lrow) * 128 + (kk0 + lkb) * 2));
                ldsm4(bB[ng], base + SM_BB + sw);
                ldsm4(bS[ng], base + SM_BS + sw);
            }
            #pragma unroll
            for (int mf = 0; mf < 2; mf++) {
                #pragma unroll
                for (int nf = 0; nf < 4; nf++) {
                    int ng = nf >> 1, sel = nf & 1;
                    mma_bf16(acc[mf][nf], aB[mf], bB[ng][sel], bB[ng][sel + 2]);
                    mma_bf16(acc[mf][nf], aB[mf], bS[ng][sel], bS[ng][sel + 2]);
                    mma_bf16(acc[mf][nf], aS[mf], bB[ng][sel], bB[ng][sel + 2]);
                }
            }
        }
    }

    // ---- epilogue: + bias, store fp32 ----
    #pragma unroll
    for (int nf = 0; nf < 4; nf++) {
        int col = n0 + nf * 8 + 2 * (lane & 3);
        float bx = __ldg(bias + col);
        float by = __ldg(bias + col + 1);
        #pragma unroll
        for (int mf = 0; mf < 2; mf++) {
            int g = row0 + m0 + mf * 16 + (lane >> 2);
            const float* a4 = acc[mf][nf];
            if (g < N_NODES) {
                float2 o = make_float2(a4[0] + bx, a4[1] + by);
                *reinterpret_cast<float2*>(out + ((size_t)t * N_NODES + g) * FEAT + col) = o;
            }
            if (g + 8 < N_NODES) {
                float2 o = make_float2(a4[2] + bx, a4[3] + by);
                *reinterpret_cast<float2*>(out + ((size_t)t * N_NODES + g + 8) * FEAT + col) = o;
            }
        }
    }
}

// ---------------------------------------------------------------------------
extern "C" void kernel_launch(void* const* d_in, const int* in_sizes, int n_in,
                              void* d_out, int out_size) {
    const float* x0     = (const float*)d_in[0];
    const float* x1     = (const float*)d_in[1];
    const float* weight = (const float*)d_in[2];
    const float* w_comp = (const float*)d_in[3];
    const float* bias   = (const float*)d_in[4];
    const int* src0 = (const int*)d_in[5];  const int* dst0 = (const int*)d_in[6];
    const int* src1 = (const int*)d_in[7];  const int* dst1 = (const int*)d_in[8];
    const int* src2 = (const int*)d_in[9];  const int* dst2 = (const int*)d_in[10];
    const int* src3 = (const int*)d_in[11]; const int* dst3 = (const int*)d_in[12];
    float* out = (float*)d_out;

    void* degptr = nullptr;
    cudaGetSymbolAddress(&degptr, g_deg);
    cudaMemsetAsync(degptr, 0, sizeof(int) * NRELS * N_NODES, 0);

    compute_w_kernel<<<256, 256>>>(weight, w_comp);

    int E0 = in_sizes[5], E1 = in_sizes[7], E2 = in_sizes[9], E3 = in_sizes[11];
    int Emax = E0;
    if (E1 > Emax) Emax = E1;
    if (E2 > Emax) Emax = E2;
    if (E3 > Emax) Emax = E3;
    dim3 egrid((unsigned)((Emax + 255) / 256), 4);
    count_kernel<<<egrid, 256>>>(dst0, dst1, dst2, dst3, E0, E1, E2, E3);
    scan_kernel<<<4, 1024>>>();
    fill_kernel<<<egrid, 256>>>(src0, dst0, src1, dst1, src2, dst2, src3, dst3,
                                E0, E1, E2, E3);

    cudaFuncSetAttribute(gemm_kernel, cudaFuncAttributeMaxDynamicSharedMemorySize, SMEM_BYTES);
    gemm_kernel<<<dim3((N_NODES + 63) / 64, 2), 256, SMEM_BYTES>>>(x0, x1, bias, out);
}

// round 12
// speedup vs baseline: 1.5815x; 1.5815x over previous
#include <cuda_runtime.h>
#include <cuda_bf16.h>
#include <cstdint>

#define N_NODES 50000
#define FEAT 128
#define NRELS 4
#define NF ((size_t)N_NODES * FEAT)

// Scratch (static __device__ — no allocation allowed)
__device__ float g_A[(size_t)NRELS * N_NODES * FEAT];       // per-relation aggregated src feats
__device__ unsigned short g_Wb[NRELS * FEAT * FEAT];        // composed W^T [r][n][k], bf16 big
__device__ unsigned short g_Ws[NRELS * FEAT * FEAT];        // composed W^T [r][n][k], bf16 small

// ---------------------------------------------------------------------------
// helpers
// ---------------------------------------------------------------------------
__device__ __forceinline__ uint32_t smem_u32(const void* p) {
    uint32_t a;
    asm("{ .reg .u64 t; cvta.to.shared.u64 t, %1; cvt.u32.u64 %0, t; }" : "=r"(a) : "l"(p));
    return a;
}
__device__ __forceinline__ unsigned short f2bf(float x) {
    return __bfloat16_as_ushort(__float2bfloat16_rn(x));
}
__device__ __forceinline__ float bf2f(unsigned short u) {
    return __uint_as_float(((uint32_t)u) << 16);
}
__device__ __forceinline__ void ldsm4(uint32_t* r, uint32_t addr) {
    asm volatile("ldmatrix.sync.aligned.m8n8.x4.shared.b16 {%0,%1,%2,%3}, [%4];"
                 : "=r"(r[0]), "=r"(r[1]), "=r"(r[2]), "=r"(r[3]) : "r"(addr));
}
__device__ __forceinline__ void mma_bf16(float* d, const uint32_t* a, uint32_t b0, uint32_t b1) {
    asm volatile(
        "mma.sync.aligned.m16n8k16.row.col.f32.bf16.bf16.f32 "
        "{%0,%1,%2,%3}, {%4,%5,%6,%7}, {%8,%9}, {%0,%1,%2,%3};"
        : "+f"(d[0]), "+f"(d[1]), "+f"(d[2]), "+f"(d[3])
        : "r"(a[0]), "r"(a[1]), "r"(a[2]), "r"(a[3]), "r"(b0), "r"(b1));
}
__device__ __forceinline__ void cp_async16(uint32_t smem_dst, const void* gsrc) {
    asm volatile("cp.async.cg.shared.global [%0], [%1], 16;"
                 :: "r"(smem_dst), "l"(gsrc) : "memory");
}
#define SWZ(off) ((off) ^ (((off) >> 3) & 0x70))

// ---------------------------------------------------------------------------
// W precompute: W^T[r][n][k] composed from bases, split to bf16 big + small
// ---------------------------------------------------------------------------
__global__ void compute_w_kernel(const float* __restrict__ weight,
                                 const float* __restrict__ w_comp) {
    int idx = blockIdx.x * blockDim.x + threadIdx.x;   // 4 * 16384, idx = r*16384 + n*128 + k
    int r = idx >> 14;
    int k = idx & 127;
    int n = (idx >> 7) & 127;
    float w = w_comp[r * 2 + 0] * weight[k * 128 + n]
            + w_comp[r * 2 + 1] * weight[16384 + k * 128 + n];
    unsigned short big = f2bf(w);
    g_Wb[idx] = big;
    g_Ws[idx] = f2bf(w - bf2f(big));
}

// ---------------------------------------------------------------------------
// Fused scatter: one launch, relation chosen per BLOCK (locality), blocks
// interleaved across relations. Each warp handles 8 edges software-batched
// (all gathers in flight before the reductions) for MLP on this
// latency-bound loop.
// ---------------------------------------------------------------------------
__global__ void __launch_bounds__(256)
scatter4_kernel(const float* __restrict__ x0, const float* __restrict__ x1,
                const int* __restrict__ s0, const int* __restrict__ d0,
                const int* __restrict__ s1, const int* __restrict__ d1,
                const int* __restrict__ s2, const int* __restrict__ d2,
                const int* __restrict__ s3, const int* __restrict__ d3,
                float* __restrict__ A,
                int E0, int E1, int E2, int E3) {
    int rel = blockIdx.x & 3;
    int e0 = (blockIdx.x >> 2) * 64 + (threadIdx.x >> 5) * 8;  // 64 edges per block
    int lane = threadIdx.x & 31;

    const float* x; const int* sp; const int* dp; int E;
    if (rel == 0)      { x = x0; sp = s0; dp = d0; E = E0; }
    else if (rel == 1) { x = x0; sp = s1; dp = d1; E = E1; }
    else if (rel == 2) { x = x1; sp = s2; dp = d2; E = E2; }
    else               { x = x1; sp = s3; dp = d3; E = E3; }
    int cnt = E - e0;
    if (cnt <= 0) return;
    if (cnt > 8) cnt = 8;
    float* Ar = A + (size_t)rel * NF;

    int s[8], d[8];
    #pragma unroll
    for (int q = 0; q < 8; q++)
        if (q < cnt) { s[q] = __ldg(sp + e0 + q); d[q] = __ldg(dp + e0 + q); }
    float4 v[8];
    #pragma unroll
    for (int q = 0; q < 8; q++)
        if (q < cnt) v[q] = __ldg(reinterpret_cast<const float4*>(x + (size_t)s[q] * FEAT) + lane);
    #pragma unroll
    for (int q = 0; q < 8; q++)
        if (q < cnt) {
            float* p = Ar + (size_t)d[q] * FEAT + lane * 4;
            asm volatile("red.global.add.v4.f32 [%0], {%1,%2,%3,%4};"
                         :: "l"(p), "f"(v[q].x), "f"(v[q].y), "f"(v[q].z), "f"(v[q].w) : "memory");
        }
}

// ---------------------------------------------------------------------------
// bf16 mma.sync GEMM with big/small compensation (3 products).
// CTA tile M=64 x N=128, K staged in 4 chunks of 64 (2 rels x 2 kchunks).
// A is read exactly once; B (256KB unique, L2-hot) is the re-read quantity.
// smem/chunk = A 16KB + B 32KB = 48KB -> occ 2. B staged via cp.async.
// Half of A chunk c+1 (one float4/thread/slot) is prefetched into registers
// before chunk c's MMAs so DRAM latency hides under compute; the other half
// is loaded at convert time behind it.
// 8 warps as 2(M) x 4(N); warp tile 32x32.
// ---------------------------------------------------------------------------
#define SM_AB 0
#define SM_AS 8192
#define SM_BB 16384
#define SM_BS 32768
#define SMEM_BYTES 49152

__global__ void __launch_bounds__(256, 2)
gemm_kernel(const float* __restrict__ bias, float* __restrict__ out) {
    extern __shared__ char smem_raw[];
    const uint32_t base = smem_u32(smem_raw);

    const int t = blockIdx.y;
    const int row0 = blockIdx.x * 64;
    const int tid = threadIdx.x;
    const int lane = tid & 31;
    const int warp = tid >> 5;
    const int m0 = (warp & 1) * 32;      // warp row offset in 64-row tile
    const int n0 = (warp >> 1) * 32;     // warp col offset in 128-col tile

    float acc[2][4][4];
    #pragma unroll
    for (int mf = 0; mf < 2; mf++)
        #pragma unroll
        for (int nf = 0; nf < 4; nf++)
            #pragma unroll
            for (int i = 0; i < 4; i++) acc[mf][nf][i] = 0.f;

    // ldmatrix lane addressing (8x8 tile rows), hoisted
    const int lrow = (lane & 7) + 8 * ((lane >> 3) & 1);
    const int lkb  = (lane >> 4) * 8;

    // per-thread A staging coordinates (j = 0,1)
    int arow[2], akq[2];
    #pragma unroll
    for (int j = 0; j < 2; j++) {
        int i = tid + j * 256;           // 0..511
        arow[j] = i >> 3;                // 0..63
        akq[j] = i & 7;
    }

    // ---- prologue: prefetch first half of A chunk 0 ----
    float4 pv0[2];
    #pragma unroll
    for (int j = 0; j < 2; j++) {
        int g = row0 + arow[j];
        pv0[j] = make_float4(0.f, 0.f, 0.f, 0.f);
        if (g < N_NODES)
            pv0[j] = __ldg(reinterpret_cast<const float4*>(
                g_A + (size_t)t * NF + (size_t)g * FEAT + akq[j] * 8));
    }

    #pragma unroll 1
    for (int c = 0; c < 4; c++) {
        const int rel = t + (c >> 1) * 2;
        const int kc = c & 1;
        const unsigned short* WBb = g_Wb + rel * FEAT * FEAT;
        const unsigned short* WSb = g_Ws + rel * FEAT * FEAT;
        const int kbase = kc * 64;

        if (c) __syncthreads();          // previous compute done before restage

        // ---- B chunk via cp.async (overlaps the A convert below) ----
        #pragma unroll
        for (int j = 0; j < 4; j++) {
            int i = tid + j * 256;            // 1024 groups of 8 bf16
            int n = i >> 3;                   // 0..127
            int kq = i & 7;
            uint32_t sw = SWZ((uint32_t)(n * 128 + kq * 16));
            cp_async16(base + SM_BB + sw, WBb + n * FEAT + kbase + kq * 8);
            cp_async16(base + SM_BS + sw, WSb + n * FEAT + kbase + kq * 8);
        }
        asm volatile("cp.async.commit_group;" ::: "memory");

        // ---- load second half + convert -> bf16 big/small -> STS ----
        #pragma unroll
        for (int j = 0; j < 2; j++) {
            int g = row0 + arow[j];
            float4 v1 = make_float4(0.f, 0.f, 0.f, 0.f);
            if (g < N_NODES)
                v1 = __ldg(reinterpret_cast<const float4*>(
                    g_A + (size_t)rel * NF + (size_t)g * FEAT + kbase + akq[j] * 8) + 1);
            float f[8] = {pv0[j].x, pv0[j].y, pv0[j].z, pv0[j].w, v1.x, v1.y, v1.z, v1.w};
            uint32_t B[4], S[4];
            #pragma unroll
            for (int q = 0; q < 4; q++) {
                unsigned short b0 = f2bf(f[2 * q]);
                unsigned short b1 = f2bf(f[2 * q + 1]);
                unsigned short s0 = f2bf(f[2 * q] - bf2f(b0));
                unsigned short s1 = f2bf(f[2 * q + 1] - bf2f(b1));
                B[q] = ((uint32_t)b1 << 16) | b0;
                S[q] = ((uint32_t)s1 << 16) | s0;
            }
            uint32_t sw = SWZ((uint32_t)(arow[j] * 128 + akq[j] * 16));
            asm volatile("st.shared.v4.b32 [%0], {%1,%2,%3,%4};"
                         :: "r"(base + SM_AB + sw), "r"(B[0]), "r"(B[1]), "r"(B[2]), "r"(B[3]) : "memory");
            asm volatile("st.shared.v4.b32 [%0], {%1,%2,%3,%4};"
                         :: "r"(base + SM_AS + sw), "r"(S[0]), "r"(S[1]), "r"(S[2]), "r"(S[3]) : "memory");
        }

        // ---- issue first-half A prefetch for chunk c+1 (hides under MMAs) ----
        if (c < 3) {
            const int nrel = t + ((c + 1) >> 1) * 2;
            const int nkbase = ((c + 1) & 1) * 64;
            #pragma unroll
            for (int j = 0; j < 2; j++) {
                int g = row0 + arow[j];
                pv0[j] = make_float4(0.f, 0.f, 0.f, 0.f);
                if (g < N_NODES)
                    pv0[j] = __ldg(reinterpret_cast<const float4*>(
                        g_A + (size_t)nrel * NF + (size_t)g * FEAT + nkbase + akq[j] * 8));
            }
        }

        asm volatile("cp.async.wait_group 0;" ::: "memory");
        __syncthreads();

        // ---- compute: 4 k16 steps ----
        #pragma unroll
        for (int ks = 0; ks < 4; ks++) {
            const int kk0 = ks * 16;

            uint32_t aB[2][4], aS[2][4];
            #pragma unroll
            for (int mf = 0; mf < 2; mf++) {
                uint32_t sw = SWZ((uint32_t)((m0 + mf * 16 + lrow) * 128 + (kk0 + lkb) * 2));
                ldsm4(aB[mf], base + SM_AB + sw);
                ldsm4(aS[mf], base + SM_AS + sw);
            }
            uint32_t bB[2][4], bS[2][4];
            #pragma unroll
            for (int ng = 0; ng < 2; ng++) {
                uint32_t sw = SWZ((uint32_t)((n0 + ng * 16 + lrow) * 128 + (kk0 + lkb) * 2));
                ldsm4(bB[ng], base + SM_BB + sw);
                ldsm4(bS[ng], base + SM_BS + sw);
            }
            #pragma unroll
            for (int mf = 0; mf < 2; mf++) {
                #pragma unroll
                for (int nf = 0; nf < 4; nf++) {
                    int ng = nf >> 1, sel = nf & 1;
                    mma_bf16(acc[mf][nf], aB[mf], bB[ng][sel], bB[ng][sel + 2]);
                    mma_bf16(acc[mf][nf], aB[mf], bS[ng][sel], bS[ng][sel + 2]);
                    mma_bf16(acc[mf][nf], aS[mf], bB[ng][sel], bB[ng][sel + 2]);
                }
            }
        }
    }

    // ---- epilogue: + bias, store fp32 ----
    #pragma unroll
    for (int nf = 0; nf < 4; nf++) {
        int col = n0 + nf * 8 + 2 * (lane & 3);
        float bx = __ldg(bias + col);
        float by = __ldg(bias + col + 1);
        #pragma unroll
        for (int mf = 0; mf < 2; mf++) {
            int g = row0 + m0 + mf * 16 + (lane >> 2);
            const float* a4 = acc[mf][nf];
            if (g < N_NODES) {
                float2 o = make_float2(a4[0] + bx, a4[1] + by);
                *reinterpret_cast<float2*>(out + ((size_t)t * N_NODES + g) * FEAT + col) = o;
            }
            if (g + 8 < N_NODES) {
                float2 o = make_float2(a4[2] + bx, a4[3] + by);
                *reinterpret_cast<float2*>(out + ((size_t)t * N_NODES + g + 8) * FEAT + col) = o;
            }
        }
    }
}

// ---------------------------------------------------------------------------
extern "C" void kernel_launch(void* const* d_in, const int* in_sizes, int n_in,
                              void* d_out, int out_size) {
    const float* x0     = (const float*)d_in[0];
    const float* x1     = (const float*)d_in[1];
    const float* weight = (const float*)d_in[2];
    const float* w_comp = (const float*)d_in[3];
    const float* bias   = (const float*)d_in[4];
    const int* src0 = (const int*)d_in[5];  const int* dst0 = (const int*)d_in[6];
    const int* src1 = (const int*)d_in[7];  const int* dst1 = (const int*)d_in[8];
    const int* src2 = (const int*)d_in[9];  const int* dst2 = (const int*)d_in[10];
    const int* src3 = (const int*)d_in[11]; const int* dst3 = (const int*)d_in[12];
    float* out = (float*)d_out;

    void* aptr = nullptr;
    cudaGetSymbolAddress(&aptr, g_A);
    float* A = (float*)aptr;

    cudaMemsetAsync(aptr, 0, sizeof(float) * NRELS * NF, 0);
    compute_w_kernel<<<256, 256>>>(weight, w_comp);

    int E0 = in_sizes[5], E1 = in_sizes[7], E2 = in_sizes[9], E3 = in_sizes[11];
    int Emax = E0;
    if (E1 > Emax) Emax = E1;
    if (E2 > Emax) Emax = E2;
    if (E3 > Emax) Emax = E3;
    int nblocks = ((Emax + 63) / 64) * 4;     // 64 edges per block, rel = bid & 3
    scatter4_kernel<<<nblocks, 256>>>(x0, x1, src0, dst0, src1, dst1,
                                      src2, dst2, src3, dst3, A,
                                      E0, E1, E2, E3);

    cudaFuncSetAttribute(gemm_kernel, cudaFuncAttributeMaxDynamicSharedMemorySize, SMEM_BYTES);
    gemm_kernel<<<dim3((N_NODES + 63) / 64, 2), 256, SMEM_BYTES>>>(bias, out);
}

// round 14
// speedup vs baseline: 1.6311x; 1.0314x over previous
#include <cuda_runtime.h>
#include <cuda_bf16.h>
#include <cstdint>

#define N_NODES 50000
#define FEAT 128
#define NRELS 4
#define NF ((size_t)N_NODES * FEAT)

// Scratch (static __device__ — no allocation allowed)
__device__ float g_A[(size_t)NRELS * N_NODES * FEAT];       // per-relation aggregated src feats
__device__ unsigned short g_Wb[NRELS * FEAT * FEAT];        // composed W^T [r][n][k], bf16 big
__device__ unsigned short g_Ws[NRELS * FEAT * FEAT];        // composed W^T [r][n][k], bf16 small

// ---------------------------------------------------------------------------
// helpers
// ---------------------------------------------------------------------------
__device__ __forceinline__ uint32_t smem_u32(const void* p) {
    uint32_t a;
    asm("{ .reg .u64 t; cvta.to.shared.u64 t, %1; cvt.u32.u64 %0, t; }" : "=r"(a) : "l"(p));
    return a;
}
__device__ __forceinline__ unsigned short f2bf(float x) {
    return __bfloat16_as_ushort(__float2bfloat16_rn(x));
}
__device__ __forceinline__ float bf2f(unsigned short u) {
    return __uint_as_float(((uint32_t)u) << 16);
}
__device__ __forceinline__ void ldsm4(uint32_t* r, uint32_t addr) {
    asm volatile("ldmatrix.sync.aligned.m8n8.x4.shared.b16 {%0,%1,%2,%3}, [%4];"
                 : "=r"(r[0]), "=r"(r[1]), "=r"(r[2]), "=r"(r[3]) : "r"(addr));
}
__device__ __forceinline__ void mma_bf16(float* d, const uint32_t* a, uint32_t b0, uint32_t b1) {
    asm volatile(
        "mma.sync.aligned.m16n8k16.row.col.f32.bf16.bf16.f32 "
        "{%0,%1,%2,%3}, {%4,%5,%6,%7}, {%8,%9}, {%0,%1,%2,%3};"
        : "+f"(d[0]), "+f"(d[1]), "+f"(d[2]), "+f"(d[3])
        : "r"(a[0]), "r"(a[1]), "r"(a[2]), "r"(a[3]), "r"(b0), "r"(b1));
}
__device__ __forceinline__ void cp_async16(uint32_t smem_dst, const void* gsrc) {
    asm volatile("cp.async.cg.shared.global [%0], [%1], 16;"
                 :: "r"(smem_dst), "l"(gsrc) : "memory");
}
#define SWZ(off) ((off) ^ (((off) >> 3) & 0x70))

// ---------------------------------------------------------------------------
// Fused init: zero g_A (all blocks) + compose/split W (first 256 blocks).
// ---------------------------------------------------------------------------
__global__ void init_kernel(const float* __restrict__ weight,
                            const float* __restrict__ w_comp) {
    int bid = blockIdx.x;
    size_t i = (size_t)bid * 256 + threadIdx.x;      // float4 index
    if (i * 4 < (size_t)NRELS * NF)
        reinterpret_cast<float4*>(g_A)[i] = make_float4(0.f, 0.f, 0.f, 0.f);
    if (bid < 256) {
        int idx = bid * 256 + threadIdx.x;           // r*16384 + n*128 + k
        int r = idx >> 14;
        int k = idx & 127;
        int n = (idx >> 7) & 127;
        float w = w_comp[r * 2 + 0] * weight[k * 128 + n]
                + w_comp[r * 2 + 1] * weight[16384 + k * 128 + n];
        unsigned short big = f2bf(w);
        g_Wb[idx] = big;
        g_Ws[idx] = f2bf(w - bf2f(big));
    }
}

// ---------------------------------------------------------------------------
// Fused scatter: one launch, relation chosen per BLOCK (locality), blocks
// interleaved across relations. Each warp handles 8 edges software-batched.
// ---------------------------------------------------------------------------
__global__ void __launch_bounds__(256)
scatter4_kernel(const float* __restrict__ x0, const float* __restrict__ x1,
                const int* __restrict__ s0, const int* __restrict__ d0,
                const int* __restrict__ s1, const int* __restrict__ d1,
                const int* __restrict__ s2, const int* __restrict__ d2,
                const int* __restrict__ s3, const int* __restrict__ d3,
                float* __restrict__ A,
                int E0, int E1, int E2, int E3) {
    int rel = blockIdx.x & 3;
    int e0 = (blockIdx.x >> 2) * 64 + (threadIdx.x >> 5) * 8;  // 64 edges per block
    int lane = threadIdx.x & 31;

    const float* x; const int* sp; const int* dp; int E;
    if (rel == 0)      { x = x0; sp = s0; dp = d0; E = E0; }
    else if (rel == 1) { x = x0; sp = s1; dp = d1; E = E1; }
    else if (rel == 2) { x = x1; sp = s2; dp = d2; E = E2; }
    else               { x = x1; sp = s3; dp = d3; E = E3; }
    int cnt = E - e0;
    if (cnt <= 0) return;
    if (cnt > 8) cnt = 8;
    float* Ar = A + (size_t)rel * NF;

    int s[8], d[8];
    #pragma unroll
    for (int q = 0; q < 8; q++)
        if (q < cnt) { s[q] = __ldg(sp + e0 + q); d[q] = __ldg(dp + e0 + q); }
    float4 v[8];
    #pragma unroll
    for (int q = 0; q < 8; q++)
        if (q < cnt) v[q] = __ldg(reinterpret_cast<const float4*>(x + (size_t)s[q] * FEAT) + lane);
    #pragma unroll
    for (int q = 0; q < 8; q++)
        if (q < cnt) {
            float* p = Ar + (size_t)d[q] * FEAT + lane * 4;
            asm volatile("red.global.add.v4.f32 [%0], {%1,%2,%3,%4};"
                         :: "l"(p), "f"(v[q].x), "f"(v[q].y), "f"(v[q].z), "f"(v[q].w) : "memory");
        }
}

// ---------------------------------------------------------------------------
// bf16 mma.sync GEMM with big/small compensation (3 products).
// CTA tile M=64 x N=128, K staged in 4 chunks of 64 (2 rels x 2 kchunks).
// SMEM: A single-buffer 16KB + B double-buffer 2x32KB = 80KB -> occ 2.
// Pipeline: B(c+1) cp.async issued before MMA(c) (wait_group 1 at use);
// first half of A(c+1) prefetched into registers before MMA(c) (half-
// prefetch: low register pressure, proven in the 180us kernel).
// 8 warps as 2(M) x 4(N); warp tile 32x32.
// ---------------------------------------------------------------------------
#define SM_AB 0
#define SM_AS 8192
#define SM_B0 16384              // buf0: big @ +0, small @ +16384
#define SM_B1 49152              // buf1: big @ +0, small @ +16384
#define SMEM_BYTES 81920

__global__ void __launch_bounds__(256, 2)
gemm_kernel(const float* __restrict__ bias, float* __restrict__ out) {
    extern __shared__ char smem_raw[];
    const uint32_t base = smem_u32(smem_raw);

    const int t = blockIdx.y;
    const int row0 = blockIdx.x * 64;
    const int tid = threadIdx.x;
    const int lane = tid & 31;
    const int warp = tid >> 5;
    const int m0 = (warp & 1) * 32;      // warp row offset in 64-row tile
    const int n0 = (warp >> 1) * 32;     // warp col offset in 128-col tile

    float acc[2][4][4];
    #pragma unroll
    for (int mf = 0; mf < 2; mf++)
        #pragma unroll
        for (int nf = 0; nf < 4; nf++)
            #pragma unroll
            for (int i = 0; i < 4; i++) acc[mf][nf][i] = 0.f;

    // ldmatrix lane addressing (8x8 tile rows), hoisted
    const int lrow = (lane & 7) + 8 * ((lane >> 3) & 1);
    const int lkb  = (lane >> 4) * 8;

    // per-thread A staging coordinates (j = 0,1)
    int arow[2], akq[2];
    #pragma unroll
    for (int j = 0; j < 2; j++) {
        int i = tid + j * 256;           // 0..511
        arow[j] = i >> 3;                // 0..63
        akq[j] = i & 7;
    }

    // B staging coordinates (j = 0..3)
    int bn[4], bkq[4];
    #pragma unroll
    for (int j = 0; j < 4; j++) {
        int i = tid + j * 256;
        bn[j] = i >> 3;                  // 0..127
        bkq[j] = i & 7;
    }

    // ---- prologue: B chunk 0 cp.async into buf0; A chunk 0 half prefetch ----
    {
        const unsigned short* WBb = g_Wb + t * FEAT * FEAT;
        const unsigned short* WSb = g_Ws + t * FEAT * FEAT;
        #pragma unroll
        for (int j = 0; j < 4; j++) {
            uint32_t sw = SWZ((uint32_t)(bn[j] * 128 + bkq[j] * 16));
            cp_async16(base + SM_B0 + sw, WBb + bn[j] * FEAT + bkq[j] * 8);
            cp_async16(base + SM_B0 + 16384 + sw, WSb + bn[j] * FEAT + bkq[j] * 8);
        }
        asm volatile("cp.async.commit_group;" ::: "memory");
    }
    float4 pv0[2];
    #pragma unroll
    for (int j = 0; j < 2; j++) {
        int g = row0 + arow[j];
        pv0[j] = make_float4(0.f, 0.f, 0.f, 0.f);
        if (g < N_NODES)
            pv0[j] = __ldg(reinterpret_cast<const float4*>(
                g_A + (size_t)t * NF + (size_t)g * FEAT + akq[j] * 8));
    }

    #pragma unroll 1
    for (int c = 0; c < 4; c++) {
        const int rel = t + (c >> 1) * 2;
        const int kbase = (c & 1) * 64;
        const uint32_t bbuf = (c & 1) ? (base + SM_B1) : (base + SM_B0);

        if (c) __syncthreads();          // previous MMAs done before A restage / B buf reuse

        // ---- load A second half + convert -> bf16 big/small -> STS ----
        #pragma unroll
        for (int j = 0; j < 2; j++) {
            int g = row0 + arow[j];
            float4 v1 = make_float4(0.f, 0.f, 0.f, 0.f);
            if (g < N_NODES)
                v1 = __ldg(reinterpret_cast<const float4*>(
                    g_A + (size_t)rel * NF + (size_t)g * FEAT + kbase + akq[j] * 8) + 1);
            float f[8] = {pv0[j].x, pv0[j].y, pv0[j].z, pv0[j].w, v1.x, v1.y, v1.z, v1.w};
            uint32_t B[4], S[4];
            #pragma unroll
            for (int q = 0; q < 4; q++) {
                unsigned short b0 = f2bf(f[2 * q]);
                unsigned short b1 = f2bf(f[2 * q + 1]);
                unsigned short s0 = f2bf(f[2 * q] - bf2f(b0));
                unsigned short s1 = f2bf(f[2 * q + 1] - bf2f(b1));
                B[q] = ((uint32_t)b1 << 16) | b0;
                S[q] = ((uint32_t)s1 << 16) | s0;
            }
            uint32_t sw = SWZ((uint32_t)(arow[j] * 128 + akq[j] * 16));
            asm volatile("st.shared.v4.b32 [%0], {%1,%2,%3,%4};"
                         :: "r"(base + SM_AB + sw), "r"(B[0]), "r"(B[1]), "r"(B[2]), "r"(B[3]) : "memory");
            asm volatile("st.shared.v4.b32 [%0], {%1,%2,%3,%4};"
                         :: "r"(base + SM_AS + sw), "r"(S[0]), "r"(S[1]), "r"(S[2]), "r"(S[3]) : "memory");
        }

        // ---- issue next chunk's B cp.async + A half prefetch ----
        if (c < 3) {
            const int nrel = t + ((c + 1) >> 1) * 2;
            const int nkbase = ((c + 1) & 1) * 64;
            const uint32_t nb = ((c + 1) & 1) ? (base + SM_B1) : (base + SM_B0);
            const unsigned short* WBb = g_Wb + nrel * FEAT * FEAT;
            const unsigned short* WSb = g_Ws + nrel * FEAT * FEAT;
            #pragma unroll
            for (int j = 0; j < 4; j++) {
                uint32_t sw = SWZ((uint32_t)(bn[j] * 128 + bkq[j] * 16));
                cp_async16(nb + sw, WBb + bn[j] * FEAT + nkbase + bkq[j] * 8);
                cp_async16(nb + 16384 + sw, WSb + bn[j] * FEAT + nkbase + bkq[j] * 8);
            }
            asm volatile("cp.async.commit_group;" ::: "memory");
            #pragma unroll
            for (int j = 0; j < 2; j++) {
                int g = row0 + arow[j];
                pv0[j] = make_float4(0.f, 0.f, 0.f, 0.f);
                if (g < N_NODES)
                    pv0[j] = __ldg(reinterpret_cast<const float4*>(
                        g_A + (size_t)nrel * NF + (size_t)g * FEAT + nkbase + akq[j] * 8));
            }
            asm volatile("cp.async.wait_group 1;" ::: "memory");   // B(c) done; B(c+1) in flight
        } else {
            asm volatile("cp.async.wait_group 0;" ::: "memory");
        }
        __syncthreads();

        // ---- compute: 4 k16 steps ----
        #pragma unroll
        for (int ks = 0; ks < 4; ks++) {
            const int kk0 = ks * 16;

            uint32_t aB[2][4], aS[2][4];
            #pragma unroll
            for (int mf = 0; mf < 2; mf++) {
                uint32_t sw = SWZ((uint32_t)((m0 + mf * 16 + lrow) * 128 + (kk0 + lkb) * 2));
                ldsm4(aB[mf], base + SM_AB + sw);
                ldsm4(aS[mf], base + SM_AS + sw);
            }
            uint32_t bB[2][4], bS[2][4];
            #pragma unroll
            for (int ng = 0; ng < 2; ng++) {
                uint32_t sw = SWZ((uint32_t)((n0 + ng * 16 + lrow) * 128 + (kk0 + lkb) * 2));
                ldsm4(bB[ng], bbuf + sw);
                ldsm4(bS[ng], bbuf + 16384 + sw);
            }
            #pragma unroll
            for (int mf = 0; mf < 2; mf++) {
                #pragma unroll
                for (int nf = 0; nf < 4; nf++) {
                    int ng = nf >> 1, sel = nf & 1;
                    mma_bf16(acc[mf][nf], aB[mf], bB[ng][sel], bB[ng][sel + 2]);
                    mma_bf16(acc[mf][nf], aB[mf], bS[ng][sel], bS[ng][sel + 2]);
                    mma_bf16(acc[mf][nf], aS[mf], bB[ng][sel], bB[ng][sel + 2]);
                }
            }
        }
    }

    // ---- epilogue: + bias, store fp32 ----
    #pragma unroll
    for (int nf = 0; nf < 4; nf++) {
        int col = n0 + nf * 8 + 2 * (lane & 3);
        float bx = __ldg(bias + col);
        float by = __ldg(bias + col + 1);
        #pragma unroll
        for (int mf = 0; mf < 2; mf++) {
            int g = row0 + m0 + mf * 16 + (lane >> 2);
            const float* a4 = acc[mf][nf];
            if (g < N_NODES) {
                float2 o = make_float2(a4[0] + bx, a4[1] + by);
                *reinterpret_cast<float2*>(out + ((size_t)t * N_NODES + g) * FEAT + col) = o;
            }
            if (g + 8 < N_NODES) {
                float2 o = make_float2(a4[2] + bx, a4[3] + by);
                *reinterpret_cast<float2*>(out + ((size_t)t * N_NODES + g + 8) * FEAT + col) = o;
            }
        }
    }
}

// ---------------------------------------------------------------------------
extern "C" void kernel_launch(void* const* d_in, const int* in_sizes, int n_in,
                              void* d_out, int out_size) {
    const float* x0     = (const float*)d_in[0];
    const float* x1     = (const float*)d_in[1];
    const float* weight = (const float*)d_in[2];
    const float* w_comp = (const float*)d_in[3];
    const float* bias   = (const float*)d_in[4];
    const int* src0 = (const int*)d_in[5];  const int* dst0 = (const int*)d_in[6];
    const int* src1 = (const int*)d_in[7];  const int* dst1 = (const int*)d_in[8];
    const int* src2 = (const int*)d_in[9];  const int* dst2 = (const int*)d_in[10];
    const int* src3 = (const int*)d_in[11]; const int* dst3 = (const int*)d_in[12];
    float* out = (float*)d_out;

    void* aptr = nullptr;
    cudaGetSymbolAddress(&aptr, g_A);
    float* A = (float*)aptr;

    // fused zero(A) + W composition (one launch)
    int zb = (int)(((size_t)NRELS * NF / 4 + 255) / 256);
    init_kernel<<<zb, 256>>>(weight, w_comp);

    int E0 = in_sizes[5], E1 = in_sizes[7], E2 = in_sizes[9], E3 = in_sizes[11];
    int Emax = E0;
    if (E1 > Emax) Emax = E1;
    if (E2 > Emax) Emax = E2;
    if (E3 > Emax) Emax = E3;
    int nblocks = ((Emax + 63) / 64) * 4;     // 64 edges per block, rel = bid & 3
    scatter4_kernel<<<nblocks, 256>>>(x0, x1, src0, dst0, src1, dst1,
                                      src2, dst2, src3, dst3, A,
                                      E0, E1, E2, E3);

    cudaFuncSetAttribute(gemm_kernel, cudaFuncAttributeMaxDynamicSharedMemorySize, SMEM_BYTES);
    gemm_kernel<<<dim3((N_NODES + 63) / 64, 2), 256, SMEM_BYTES>>>(bias, out);
}